// round 2
// baseline (speedup 1.0000x reference)
#include <cuda_runtime.h>
#include <math.h>

// ---------------------------------------------------------------------------
// SpatialDecoderGMM — round 2
//   proj:   x_in[N,161] @ W_in -> g_xin[N,64]
//   CSR:    degree/count -> scan -> fill (per-launch, atomic-free aggregation)
//   gather: one warp per (node, dir): g_ofob[N,128]
//   fused:  filter GEMM + head GEMM + softplus/softmax, writes gmm_out & out1
// Output: gmm_out[N*96] | out1[N*128] | h[N*64]
// ---------------------------------------------------------------------------

#define MAXN 100000
#define MAXE 1600000

__device__ __align__(16) float g_xin [MAXN * 64];
__device__ __align__(16) float g_ofob[MAXN * 128];
__device__ float g_degw[2 * MAXN];       // [0,N): deg_f (by tgt), [N,2N): deg_b (by src)
__device__ int   g_cnt [2 * MAXN];
__device__ int   g_off [2 * MAXN];
__device__ int   g_cur [2 * MAXN];
__device__ __align__(16) int2 g_csr[2 * MAXE];   // (neighbor, weight-bits)
__device__ int   g_bsum[256];
__device__ int   g_boff[256];
__device__ __align__(16) float g_Whead[128 * 96];
__device__ float g_bhead[96];

// ---------------------------------------------------------------------------
__global__ void pack_head_kernel(const float* __restrict__ Wmu, const float* __restrict__ bmu,
                                 const float* __restrict__ Wsg, const float* __restrict__ bsg,
                                 const float* __restrict__ Wpi, const float* __restrict__ bpi) {
    int idx = blockIdx.x * blockDim.x + threadIdx.x;
    if (idx < 128 * 32) {
        int i = idx >> 5, k = idx & 31;
        g_Whead[i * 96 + k]      = Wmu[idx];
        g_Whead[i * 96 + 32 + k] = Wsg[idx];
        g_Whead[i * 96 + 64 + k] = Wpi[idx];
    }
    if (idx < 32) {
        g_bhead[idx]      = bmu[idx];
        g_bhead[32 + idx] = bsg[idx];
        g_bhead[64 + idx] = bpi[idx];
    }
}

// ---------------------------------------------------------------------------
// Input projection: [x | x_hat_1 | h] @ W_in + b_in -> g_xin
// ---------------------------------------------------------------------------
__global__ void proj_kernel(const float* __restrict__ x, const float* __restrict__ xh,
                            const float* __restrict__ h, const float* __restrict__ Win,
                            const float* __restrict__ bin, int N) {
    extern __shared__ float sm[];
    float* sW = sm;                 // 161*64
    float* sB = sW + 161 * 64;      // 64
    float* sX = sB + 64;            // 32*163

    const int tid = threadIdx.x;
    for (int idx = tid; idx < 161 * 64; idx += 256) sW[idx] = Win[idx];
    if (tid < 64) sB[tid] = bin[tid];

    int node0 = blockIdx.x * 32;
    for (int idx = tid; idx < 32 * 161; idx += 256) {
        int n = idx / 161, i = idx % 161;
        int g = node0 + n;
        float v = 0.f;
        if (g < N) {
            if (i == 0)       v = x[g];
            else if (i < 97)  v = xh[(size_t)g * 96 + (i - 1)];
            else              v = h[(size_t)g * 64 + (i - 97)];
        }
        sX[n * 163 + i] = v;
    }
    __syncthreads();

    int c4 = tid & 15;
    int sub = tid >> 4;
    const float4* sW4 = reinterpret_cast<const float4*>(sW);
    float4 bb = reinterpret_cast<const float4*>(sB)[c4];
    float4 acc0 = bb, acc1 = bb;
    int n0 = sub * 2, n1 = n0 + 1;

    #pragma unroll 4
    for (int i = 0; i < 161; i++) {
        float4 w = sW4[i * 16 + c4];
        float x0 = sX[n0 * 163 + i];
        float x1 = sX[n1 * 163 + i];
        acc0.x += x0 * w.x; acc0.y += x0 * w.y; acc0.z += x0 * w.z; acc0.w += x0 * w.w;
        acc1.x += x1 * w.x; acc1.y += x1 * w.y; acc1.z += x1 * w.z; acc1.w += x1 * w.w;
    }
    int g0 = node0 + n0, g1 = node0 + n1;
    if (g0 < N) reinterpret_cast<float4*>(g_xin)[(size_t)g0 * 16 + c4] = acc0;
    if (g1 < N) reinterpret_cast<float4*>(g_xin)[(size_t)g1 * 16 + c4] = acc1;
}

// ---------------------------------------------------------------------------
// CSR build
// ---------------------------------------------------------------------------
__global__ void degree_count_kernel(const int* __restrict__ ei, const float* __restrict__ ew,
                                    int E, int N) {
    int e = blockIdx.x * blockDim.x + threadIdx.x;
    if (e >= E) return;
    int s = ei[e], t = ei[E + e];
    float w = ew[e];
    if (s == t || w == 0.f) return;
    atomicAdd(&g_degw[t], w);
    atomicAdd(&g_degw[N + s], w);
    atomicAdd(&g_cnt[t], 1);
    atomicAdd(&g_cnt[N + s], 1);
}

__global__ void scan1_kernel(int total) {
    __shared__ int sh[256];
    int tid = threadIdx.x;
    int base = blockIdx.x * 2048 + tid * 8;
    int v[8]; int s = 0;
    #pragma unroll
    for (int k = 0; k < 8; k++) { int i = base + k; v[k] = (i < total) ? g_cnt[i] : 0; s += v[k]; }
    sh[tid] = s; __syncthreads();
    for (int o = 1; o < 256; o <<= 1) {
        int xv = (tid >= o) ? sh[tid - o] : 0;
        __syncthreads(); sh[tid] += xv; __syncthreads();
    }
    if (tid == 255) g_bsum[blockIdx.x] = sh[255];
    int excl = sh[tid] - s;
    #pragma unroll
    for (int k = 0; k < 8; k++) { int i = base + k; if (i < total) g_off[i] = excl; excl += v[k]; }
}

__global__ void scan2_kernel(int nb) {
    __shared__ int sh[256];
    int tid = threadIdx.x;
    int s = (tid < nb) ? g_bsum[tid] : 0;
    sh[tid] = s; __syncthreads();
    for (int o = 1; o < 256; o <<= 1) {
        int xv = (tid >= o) ? sh[tid - o] : 0;
        __syncthreads(); sh[tid] += xv; __syncthreads();
    }
    if (tid < nb) g_boff[tid] = sh[tid] - s;
}

__global__ void scan3_kernel(int total) {
    int i = blockIdx.x * blockDim.x + threadIdx.x;
    if (i >= total) return;
    int o = g_off[i] + g_boff[i >> 11];
    g_off[i] = o;
    g_cur[i] = o;
}

__global__ void fill_kernel(const int* __restrict__ ei, const float* __restrict__ ew,
                            int E, int N) {
    int e = blockIdx.x * blockDim.x + threadIdx.x;
    if (e >= E) return;
    int s = ei[e], t = ei[E + e];
    float w = ew[e];
    if (s == t || w == 0.f) return;
    int wi = __float_as_int(w);
    int p = atomicAdd(&g_cur[t], 1);
    g_csr[p] = make_int2(s, wi);
    int q = atomicAdd(&g_cur[N + s], 1);
    g_csr[q] = make_int2(t, wi);
}

// ---------------------------------------------------------------------------
// Gather: one warp per (node, direction). Register fp32 accumulation, no atomics.
// ---------------------------------------------------------------------------
__global__ void gather_kernel(int N) {
    int warp = (blockIdx.x * blockDim.x + threadIdx.x) >> 5;
    int lane = threadIdx.x & 31;
    if (warp >= 2 * N) return;
    int row  = warp;
    int node = (row < N) ? row : row - N;
    int half = (row < N) ? 0 : 64;
    int base = g_off[row];
    int cnt  = g_cnt[row];
    float dw = g_degw[row];
    float inv = 1.f / (dw > 0.f ? dw : 1.f);

    float a0 = 0.f, a1 = 0.f;
    int e = 0;
    for (; e + 2 <= cnt; e += 2) {
        int2 r0 = g_csr[base + e];
        int2 r1 = g_csr[base + e + 1];
        float w0 = __int_as_float(r0.y), w1 = __int_as_float(r1.y);
        const float* p0 = g_xin + (size_t)r0.x * 64;
        const float* p1 = g_xin + (size_t)r1.x * 64;
        float v00 = p0[lane], v01 = p0[lane + 32];
        float v10 = p1[lane], v11 = p1[lane + 32];
        a0 += w0 * v00 + w1 * v10;
        a1 += w0 * v01 + w1 * v11;
    }
    if (e < cnt) {
        int2 r = g_csr[base + e];
        float w = __int_as_float(r.y);
        const float* p = g_xin + (size_t)r.x * 64;
        a0 += w * p[lane];
        a1 += w * p[lane + 32];
    }
    float* o = g_ofob + (size_t)node * 128 + half;
    o[lane]      = a0 * inv;
    o[lane + 32] = a1 * inv;
}

// ---------------------------------------------------------------------------
// Fused dense: out64 = ofob@Wf+bf; out1=[out64|h]; raw = out1@Whead+bhead;
// softplus/softmax; writes gmm_out and out1 directly to d_out.
// 512 threads, 64 nodes per block.
// ---------------------------------------------------------------------------
__global__ void __launch_bounds__(512)
fused_dense_kernel(const float* __restrict__ h,
                   const float* __restrict__ Wf, const float* __restrict__ bf,
                   float* __restrict__ out, int N) {
    extern __shared__ float sm[];
    float* sWf = sm;               // 128*64 = 8192
    float* sWh = sWf + 8192;       // 128*96 = 12288
    float* sBf = sWh + 12288;      // 64
    float* sBh = sBf + 64;         // 96
    float* sIn = sBh + 96;         // 64*132 (aliased as sRaw stride 104 later)
    float* sO1 = sIn + 64 * 132;   // 64*132

    const int tid = threadIdx.x;
    const int node0 = blockIdx.x * 64;

    for (int i = tid; i < 8192; i += 512)  sWf[i] = Wf[i];
    for (int i = tid; i < 12288; i += 512) sWh[i] = g_Whead[i];
    if (tid < 64) sBf[tid] = bf[tid];
    if (tid < 96) sBh[tid] = g_bhead[tid];

    for (int idx = tid; idx < 64 * 128; idx += 512) {
        int n = idx >> 7, c = idx & 127;
        int g = node0 + n;
        sIn[n * 132 + c] = (g < N) ? g_ofob[(size_t)g * 128 + c] : 0.f;
    }
    for (int idx = tid; idx < 64 * 64; idx += 512) {
        int n = idx >> 6, j = idx & 63;
        int g = node0 + n;
        sO1[n * 132 + 64 + j] = (g < N) ? h[(size_t)g * 64 + j] : 0.f;
    }
    __syncthreads();

    const int cg = tid & 7;
    const int nn = tid >> 3;      // node 0..63

    // ---- phase 1: filter GEMM (8 cols/thread) ----
    {
        const float4* sWf4 = reinterpret_cast<const float4*>(sWf);
        float4 a0 = reinterpret_cast<const float4*>(sBf)[cg * 2];
        float4 a1 = reinterpret_cast<const float4*>(sBf)[cg * 2 + 1];
        #pragma unroll 4
        for (int i = 0; i < 128; i++) {
            float4 w0 = sWf4[i * 16 + cg * 2];
            float4 w1 = sWf4[i * 16 + cg * 2 + 1];
            float xv = sIn[nn * 132 + i];
            a0.x += xv * w0.x; a0.y += xv * w0.y; a0.z += xv * w0.z; a0.w += xv * w0.w;
            a1.x += xv * w1.x; a1.y += xv * w1.y; a1.z += xv * w1.z; a1.w += xv * w1.w;
        }
        float4* dst = reinterpret_cast<float4*>(sO1 + nn * 132 + cg * 8);
        dst[0] = a0; dst[1] = a1;
    }
    __syncthreads();

    // ---- write out1 tile to global ----
    float* out1g = out + (size_t)N * 96;
    for (int idx = tid; idx < 64 * 128; idx += 512) {
        int n = idx >> 7, c = idx & 127;
        int g = node0 + n;
        if (g < N) out1g[(size_t)g * 128 + c] = sO1[n * 132 + c];
    }

    // ---- phase 2: head GEMM (12 cols/thread) ----
    float* sRaw = sIn;   // alias; sIn is dead now
    {
        const float4* sWh4 = reinterpret_cast<const float4*>(sWh);
        float4 a0 = reinterpret_cast<const float4*>(sBh)[cg * 3];
        float4 a1 = reinterpret_cast<const float4*>(sBh)[cg * 3 + 1];
        float4 a2 = reinterpret_cast<const float4*>(sBh)[cg * 3 + 2];
        #pragma unroll 2
        for (int i = 0; i < 128; i++) {
            float4 w0 = sWh4[i * 24 + cg * 3];
            float4 w1 = sWh4[i * 24 + cg * 3 + 1];
            float4 w2 = sWh4[i * 24 + cg * 3 + 2];
            float xv = sO1[nn * 132 + i];
            a0.x += xv * w0.x; a0.y += xv * w0.y; a0.z += xv * w0.z; a0.w += xv * w0.w;
            a1.x += xv * w1.x; a1.y += xv * w1.y; a1.z += xv * w1.z; a1.w += xv * w1.w;
            a2.x += xv * w2.x; a2.y += xv * w2.y; a2.z += xv * w2.z; a2.w += xv * w2.w;
        }
        float4* dst = reinterpret_cast<float4*>(sRaw + nn * 104 + cg * 12);
        dst[0] = a0; dst[1] = a1; dst[2] = a2;
    }
    __syncthreads();

    // ---- phase 3: softplus(sigma), softmax(pi), write gmm_out ----
    {
        int w = tid >> 5, lane = tid & 31;
        #pragma unroll
        for (int p = 0; p < 4; p++) {
            int n = w * 4 + p;
            int g = node0 + n;
            if (g >= N) continue;
            float mu = sRaw[n * 104 + lane];
            float sg = sRaw[n * 104 + 32 + lane];
            float pl = sRaw[n * 104 + 64 + lane];
            float sp = (sg > 20.f) ? sg : log1pf(expf(sg));
            float m = pl;
            #pragma unroll
            for (int o = 16; o; o >>= 1) m = fmaxf(m, __shfl_xor_sync(0xFFFFFFFFu, m, o));
            float e2 = expf(pl - m);
            float ss = e2;
            #pragma unroll
            for (int o = 16; o; o >>= 1) ss += __shfl_xor_sync(0xFFFFFFFFu, ss, o);
            float pi = e2 / ss;
            float* og = out + (size_t)g * 96;
            og[lane]      = mu;
            og[32 + lane] = sp;
            og[64 + lane] = pi;
        }
    }
}

// ---------------------------------------------------------------------------
extern "C" void kernel_launch(void* const* d_in, const int* in_sizes, int n_in,
                              void* d_out, int out_size) {
    const float* x   = (const float*)d_in[0];
    const float* xh  = (const float*)d_in[1];
    const float* h   = (const float*)d_in[2];
    const int*   ei  = (const int*)  d_in[3];
    const float* ew  = (const float*)d_in[4];
    const float* Win = (const float*)d_in[5];
    const float* bin = (const float*)d_in[6];
    const float* Wf  = (const float*)d_in[7];
    const float* bf  = (const float*)d_in[8];
    const float* Wmu = (const float*)d_in[9];
    const float* bmu = (const float*)d_in[10];
    const float* Wsg = (const float*)d_in[11];
    const float* bsg = (const float*)d_in[12];
    const float* Wpi = (const float*)d_in[13];
    const float* bpi = (const float*)d_in[14];

    int N = in_sizes[0];
    int E = in_sizes[3] / 2;
    if (N > MAXN) N = MAXN;
    if (E > MAXE) E = MAXE;
    float* out = (float*)d_out;

    void *p_degw, *p_cnt;
    cudaGetSymbolAddress(&p_degw, g_degw);
    cudaGetSymbolAddress(&p_cnt,  g_cnt);
    cudaMemsetAsync(p_degw, 0, (size_t)2 * N * sizeof(float));
    cudaMemsetAsync(p_cnt,  0, (size_t)2 * N * sizeof(int));

    pack_head_kernel<<<(128 * 32 + 255) / 256, 256>>>(Wmu, bmu, Wsg, bsg, Wpi, bpi);

    // input projection
    size_t sh_proj = (size_t)(161 * 64 + 64 + 32 * 163) * sizeof(float);
    cudaFuncSetAttribute(proj_kernel, cudaFuncAttributeMaxDynamicSharedMemorySize, (int)sh_proj);
    proj_kernel<<<(N + 31) / 32, 256, sh_proj>>>(x, xh, h, Win, bin, N);

    // CSR build
    degree_count_kernel<<<(E + 255) / 256, 256>>>(ei, ew, E, N);
    int total = 2 * N;
    int nb = (total + 2047) / 2048;
    scan1_kernel<<<nb, 256>>>(total);
    scan2_kernel<<<1, 256>>>(nb);
    scan3_kernel<<<(total + 255) / 256, 256>>>(total);
    fill_kernel<<<(E + 255) / 256, 256>>>(ei, ew, E, N);

    // gather aggregation
    gather_kernel<<<(2 * N + 7) / 8, 256>>>(N);

    // fused dense + heads + activations
    size_t sh_fused = (size_t)(8192 + 12288 + 64 + 96 + 64 * 132 + 64 * 132) * sizeof(float);
    cudaFuncSetAttribute(fused_dense_kernel, cudaFuncAttributeMaxDynamicSharedMemorySize, (int)sh_fused);
    fused_dense_kernel<<<(N + 63) / 64, 512, sh_fused>>>(h, Wf, bf, out, N);

    // h passthrough
    size_t off2 = (size_t)N * 96 + (size_t)N * 128;
    if ((size_t)out_size >= off2 + (size_t)N * 64)
        cudaMemcpyAsync(out + off2, h, (size_t)N * 64 * sizeof(float),
                        cudaMemcpyDeviceToDevice);
}